// round 13
// baseline (speedup 1.0000x reference)
#include <cuda_runtime.h>
#include <cstdint>

#define BB 16
#define LL 2048
#define DD 64
#define DLAT 32
#define KK 16
#define DN 128

#define SQCF 0.70710678118654752440f

// ---------------- f32x2 helpers (sm_100+) ----------------
#define PACKF2(d, a, b) asm("mov.b64 %0, {%1, %2};" : "=l"(d) : "f"(a), "f"(b))
#define FMAF2(d, a, b)  asm("fma.rn.f32x2 %0, %1, %2, %0;" : "+l"(d) : "l"(a), "l"(b))
#define UNPKF2(lo, hi, d) asm("mov.b64 {%0, %1}, %2;" : "=f"(lo), "=f"(hi) : "l"(d))

// ---------------- scratch (device globals) ----------------
__device__ float g_v[BB * KK * LL];                      // 2 MB
__device__ float g_det[BB * KK * 1920];                  // 2 MB
__device__ float g_app[BB * KK * 1920];                  // 2 MB
__device__ float g_curA[(size_t)BB * DLAT * KK * DN];    // 4 MB (dense output)
__device__ float g_sum[(size_t)4 * BB * DLAT * LL];      // 16 MB (per-kquarter sums)

// ---------------- K2: fused z + v ----------------
__global__ void __launch_bounds__(128) k_v(const float* __restrict__ seq,
                                           const float* __restrict__ Wg,
                                           const float* __restrict__ coeffs,
                                           const float* __restrict__ tme,
                                           const float* __restrict__ ts,
                                           const float* __restrict__ Wh, int Lts) {
    __shared__ __align__(16) float sWh[32 * 256];   // 32 KB (also staging for Wg|seq)
    __shared__ float sder[32 * 65];
    __shared__ __align__(16) float sz[32 * 36];     // z rows, padded stride 36
    __shared__ int   si[32];
    __shared__ float sinv[32];

    int tid = threadIdx.x;
    int b   = blockIdx.x >> 6;
    int l0  = (blockIdx.x & 63) << 5;

    for (int e = tid; e < 2048; e += 128) sWh[e] = Wg[e];
    {
        const float4* sp = (const float4*)(seq + ((size_t)b * LL + l0) * DD);
        for (int e = tid; e < 512; e += 128) ((float4*)(sWh + 2048))[e] = sp[e];
    }
    if (tid < 32) {
        float t = tme[l0 + tid];
        int lo = 0, hi = Lts;
        while (lo < hi) { int mid = (lo + hi) >> 1; if (ts[mid] <= t) lo = mid + 1; else hi = mid; }
        int i = lo - 1;
        if (i < 0) i = 0;
        if (i > Lts - 2) i = Lts - 2;
        si[tid]   = i;
        sinv[tid] = 1.f / (ts[i + 1] - ts[i]);
    }
    __syncthreads();

    for (int e = tid; e < 1024; e += 128) {
        int r = e >> 5, j = e & 31;
        float acc = 0.f;
#pragma unroll
        for (int Dd = 0; Dd < DD; ++Dd)
            acc += sWh[2048 + r * DD + Dd] * sWh[Dd * DLAT + j];
        sz[r * 36 + j] = fmaxf(acc, 0.f);
    }
    for (int e = tid; e < 2048; e += 128) {
        int lt = e >> 6, Dg = e & 63;
        int i  = si[lt];
        float a = coeffs[((size_t)b * LL + i + 1) * DD + Dg];
        float c = coeffs[((size_t)b * LL + i) * DD + Dg];
        sder[lt * 65 + Dg] = (a - c) * sinv[lt];
    }
    __syncthreads();

    int kkq = tid & 3;
    int kk0 = kkq * 4;
    int lt  = tid >> 2;

    unsigned long long zs[32];
    {
        const float4* zp = (const float4*)(sz + lt * 36);
#pragma unroll
        for (int q = 0; q < 8; ++q) {
            float4 z4 = zp[q];
            PACKF2(zs[q * 4 + 0], z4.x, z4.x);
            PACKF2(zs[q * 4 + 1], z4.y, z4.y);
            PACKF2(zs[q * 4 + 2], z4.z, z4.z);
            PACKF2(zs[q * 4 + 3], z4.w, z4.w);
        }
    }

    float acc0 = 0.f, acc1 = 0.f, acc2 = 0.f, acc3 = 0.f;
#pragma unroll 1
    for (int ch = 0; ch < 4; ++ch) {
        __syncthreads();
        const float4* src4 = (const float4*)Wh + ch * 64;
        for (int e = tid; e < 2048; e += 128) {
            int ddr = e >> 6, c4 = e & 63;
            ((float4*)sWh)[ddr * 64 + c4] = src4[(size_t)ddr * 256 + c4];
        }
        __syncthreads();
#pragma unroll 2
        for (int Dl = 0; Dl < 16; ++Dl) {
            unsigned long long h01 = 0ULL, h23 = 0ULL;
            const ulonglong2* wb = reinterpret_cast<const ulonglong2*>(sWh + Dl * 16 + kk0);
#pragma unroll
            for (int ddq = 0; ddq < 32; ++ddq) {
                ulonglong2 w = wb[ddq * 64];
                FMAF2(h01, zs[ddq], w.x);
                FMAF2(h23, zs[ddq], w.y);
            }
            float f0, f1, f2, f3;
            UNPKF2(f0, f1, h01);
            UNPKF2(f2, f3, h23);
            float dv = sder[lt * 65 + ch * 16 + Dl];
            acc0 += fmaxf(f0, 0.f) * dv;
            acc1 += fmaxf(f1, 0.f) * dv;
            acc2 += fmaxf(f2, 0.f) * dv;
            acc3 += fmaxf(f3, 0.f) * dv;
        }
    }
    size_t vb = (size_t)b * KK;
    g_v[(vb + kk0 + 0) * LL + l0 + lt] = acc0;
    g_v[(vb + kk0 + 1) * LL + l0 + lt] = acc1;
    g_v[(vb + kk0 + 2) * LL + l0 + lt] = acc2;
    g_v[(vb + kk0 + 3) * LL + l0 + lt] = acc3;
}

// ---------------- K3: 4-level Haar decomposition ----------------
__global__ void k_haar() {
    __shared__ float s0[2048];
    __shared__ float s1[1024];
    int bk  = blockIdx.x;
    int tid = threadIdx.x;
    const float* row = g_v + (size_t)bk * LL;
    for (int i = tid; i < 2048; i += 128) s0[i] = row[i];
    __syncthreads();
    int n = 2048, off = 0;
    float* src = s0;
    float* dst = s1;
    for (int lev = 0; lev < 4; ++lev) {
        int half = n >> 1;
        for (int t = tid; t < half; t += 128) {
            float a = src[2 * t], bv = src[2 * t + 1];
            float cA = (a + bv) * SQCF;
            float cD = (a - bv) * SQCF;
            dst[t] = cA;
            g_det[(size_t)bk * 1920 + off + t] = cD;
            g_app[(size_t)bk * 1920 + off + t] = cA;
        }
        __syncthreads();
        off += half; n = half;
        float* tmp = src; src = dst; dst = tmp;
    }
}

// ---------------- K4: fused 3-round dense chain (R10 version) --------
__global__ void __launch_bounds__(256) k_dense3(const float* __restrict__ W) {
    __shared__ __align__(16) float sx[2][128 * 20];   // 20.5 KB
    __shared__ __align__(16) float Ws[128 * 36];      // 18.4 KB
    int tid = threadIdx.x;
    int dd  = blockIdx.x >> 4;
    int kk  = blockIdx.x & 15;
    int t   = tid & 127;
    int bh  = tid >> 7;
    int prow = tid >> 3;
    int pc4  = tid & 7;

    for (int e = tid; e < 2048; e += 256) {
        int b = e >> 7, q = e & 127;
        sx[0][q * 20 + b] = g_app[(size_t)(b * 16 + kk) * 1920 + 1792 + q];
    }

    int src = 0;
#pragma unroll 1
    for (int r = 0; r < 3; ++r) {
        const float4* Wr4 = (const float4*)(W + ((size_t)r * 512 + dd * 16 + kk) * (DN * DN));
        float4 pf[4];
#pragma unroll
        for (int i = 0; i < 4; ++i)
            pf[i] = Wr4[(prow + i * 32) * 32 + pc4];

        unsigned long long a0 = 0ULL, a1 = 0ULL, a2 = 0ULL, a3 = 0ULL;
#pragma unroll 1
        for (int ch = 0; ch < 4; ++ch) {
            __syncthreads();
#pragma unroll
            for (int i = 0; i < 4; ++i)
                *(float4*)&Ws[(prow + i * 32) * 36 + pc4 * 4] = pf[i];
            if (ch < 3) {
#pragma unroll
                for (int i = 0; i < 4; ++i)
                    pf[i] = Wr4[(prow + i * 32) * 32 + (ch + 1) * 8 + pc4];
            }
            __syncthreads();
#pragma unroll
            for (int q4 = 0; q4 < 8; ++q4) {
                float4 w = *(const float4*)&Ws[t * 36 + q4 * 4];
                int qb = (ch * 8 + q4) * 4;
#pragma unroll
                for (int s = 0; s < 4; ++s) {
                    float wv = (s == 0) ? w.x : (s == 1) ? w.y : (s == 2) ? w.z : w.w;
                    unsigned long long ws;
                    PACKF2(ws, wv, wv);
                    const ulonglong2* xv =
                        (const ulonglong2*)&sx[src][(qb + s) * 20 + bh * 8];
                    ulonglong2 xa = xv[0];
                    FMAF2(a0, ws, xa.x);
                    FMAF2(a1, ws, xa.y);
                    ulonglong2 xb2 = xv[1];
                    FMAF2(a2, ws, xb2.x);
                    FMAF2(a3, ws, xb2.y);
                }
            }
        }
        float f0, f1, f2, f3, f4, f5, f6, f7;
        UNPKF2(f0, f1, a0); UNPKF2(f2, f3, a1);
        UNPKF2(f4, f5, a2); UNPKF2(f6, f7, a3);
        if (r < 2) {
            int ds = src ^ 1;
            *(float4*)&sx[ds][t * 20 + bh * 8]     = make_float4(f0, f1, f2, f3);
            *(float4*)&sx[ds][t * 20 + bh * 8 + 4] = make_float4(f4, f5, f6, f7);
            src = ds;
        } else {
            float f[8] = {f0, f1, f2, f3, f4, f5, f6, f7};
#pragma unroll
            for (int i = 0; i < 8; ++i) {
                int b = bh * 8 + i;
                g_curA[(((size_t)b * 32 + dd) * 16 + kk) * DN + t] = f[i];
            }
        }
    }
}

// ---------------- K5: fused wavelet reconstruction (channel-interleaved) ------
// block = (b, dd, kq); 4 kk per block; cur[4][2048] in SMEM across all levels.
// xb buffers hold channel-INTERLEAVED rows: row kg = (Ll+4) float2 of (ch0,ch1).
// wpk holds (w_o[f], u_o[f]) tap pairs + (bias_o, 0):
//   u64 index ((j*G+kg)*8+seg)*12 + o*6 + f ; f<5 taps, f==5 bias.
// smem floats: cur 8192 | xb 2*2112 | wpk 2304  => 58,880 B (3 CTAs/SM ok)

template <int Ll, int G, int OFF>
__device__ __forceinline__ void lc_level(int tid, int b, int dd, int kq,
                                         float* __restrict__ cur,
                                         float* __restrict__ xb,
                                         float* __restrict__ wpk,
                                         const float* __restrict__ lc_w,
                                         const float* __restrict__ lc_b,
                                         int lev) {
    constexpr int rs = Ll + 4;          // row stride in float2 units
    constexpr int R = Ll >> 3;
    constexpr int ng = 4 / G;
    constexpr int total = (G * Ll) >> 2;
    constexpr int lq = Ll >> 2;

    __syncthreads();
    for (int e = tid; e < 2 * 2112; e += 256) xb[e] = 0.f;

#pragma unroll 1
    for (int grp = 0; grp < ng; ++grp) {
        int kg0 = grp * G;
        __syncthreads();
        // pack weight pairs (w_o[f], u_o[f]) and bias (b_o, 0)
        constexpr int P = 3 * G * 96;   // u64 entries = 3*G*8*12
        for (int e = tid; e < P; e += 256) {
            int j  = e / (G * 96);
            int r2 = e - j * (G * 96);
            int kg = r2 / 96;
            int r3 = r2 - kg * 96;
            int seg = r3 / 12;
            int q   = r3 - seg * 12;
            int o   = q / 6;
            int f   = q - o * 6;
            int kk  = kq * 4 + kg0 + kg;
            size_t base = ((size_t)((lev * 3 + j) * 32 + dd) * 16 + kk);
            float lo, hi;
            if (f < 5) {
                lo = lc_w[base * 160 + o * 80 + seg * 5 + f];        // a-tap
                hi = lc_w[base * 160 + o * 80 + 40 + seg * 5 + f];   // c-tap
            } else {
                lo = lc_b[base * 16 + o * 8 + seg];
                hi = 0.f;
            }
            ((float2*)wpk)[e] = make_float2(lo, hi);
        }
        // init interleaved rows (interior at float2 index +2): (det, app)
        for (int e = tid; e < G * Ll; e += 256) {
            int kg = e / Ll, t = e - kg * Ll;
            int kk = kq * 4 + kg0 + kg;
            float dv = g_det[(size_t)(b * 16 + kk) * 1920 + OFF + t];
            float av = g_app[(size_t)(b * 16 + kk) * 1920 + OFF + t];
            ((float2*)xb)[kg * rs + 2 + t] = make_float2(dv, av);
        }
        __syncthreads();

        int srcb = 0;
#pragma unroll 1
        for (int j = 0; j < 3; ++j) {
            if (tid < total) {
                int kg = tid / lq;
                int t0 = (tid - kg * lq) << 2;
                int seg = t0 / R;
                const unsigned long long* wp =
                    (const unsigned long long*)wpk + ((size_t)((j * G + kg) * 8 + seg)) * 12;
                unsigned long long W0[5], W1[5];
#pragma unroll
                for (int f = 0; f < 5; ++f) { W0[f] = wp[f]; W1[f] = wp[6 + f]; }
                unsigned long long B0 = wp[5], B1 = wp[11];

                // 8 interleaved taps = 4 LDS.128
                const float2* sp = (const float2*)(xb + srcb * 2112) + kg * rs + t0;
                unsigned long long Pt[8];
#pragma unroll
                for (int i4 = 0; i4 < 4; ++i4) {
                    ulonglong2 v = ((const ulonglong2*)sp)[i4];
                    Pt[2 * i4]     = v.x;
                    Pt[2 * i4 + 1] = v.y;
                }

                float2* dp = (float2*)(xb + (srcb ^ 1) * 2112) + kg * rs + 2 + t0;
#pragma unroll
                for (int p = 0; p < 4; ++p) {
                    unsigned long long a0 = B0, a1 = B1;
#pragma unroll
                    for (int f = 0; f < 5; ++f) {
                        FMAF2(a0, W0[f], Pt[p + f]);
                        FMAF2(a1, W1[f], Pt[p + f]);
                    }
                    float l0, h0, l1, h1;
                    UNPKF2(l0, h0, a0);
                    UNPKF2(l1, h1, a1);
                    dp[p] = make_float2(fmaxf(l0 + h0, 0.f), fmaxf(l1 + h1, 0.f));
                }
            }
            __syncthreads();
            srcb ^= 1;
        }

        // combine + haar_rec (srcb == 1 => final interleaved data in xb[2112..])
        constexpr int nel = G * Ll;
        float2 rv[4];
        int cnt = 0;
        for (int e = tid; e < nel; e += 256) {
            int kg = e / Ll, t = e - kg * Ll;
            float2 X = ((const float2*)(xb + 2112))[kg * rs + 2 + t];
            float X0 = X.x;
            float X1 = X.y + cur[(kg0 + kg) * 2048 + t];
            rv[cnt++] = make_float2((X1 + X0) * SQCF, (X1 - X0) * SQCF);
        }
        __syncthreads();
        cnt = 0;
        for (int e = tid; e < nel; e += 256) {
            int kg = e / Ll, t = e - kg * Ll;
            *(float2*)&cur[(kg0 + kg) * 2048 + 2 * t] = rv[cnt++];
        }
        __syncthreads();
    }
}

__global__ void __launch_bounds__(256, 3) k_wave(const float* __restrict__ lc_w,
                                                 const float* __restrict__ lc_b) {
    extern __shared__ float sm[];
    float* cur = sm;                 // 4*2048 = 8192
    float* xb  = sm + 8192;          // 2*2112 = 4224
    float* wpk = sm + 8192 + 4224;   // 2304

    int tid = threadIdx.x;
    int kq  = blockIdx.x & 3;
    int dd  = (blockIdx.x >> 2) & 31;
    int b   = blockIdx.x >> 7;

    for (int e = tid; e < 512; e += 256) {
        int kg = e >> 7, q = e & 127;
        cur[kg * 2048 + q] =
            g_curA[(((size_t)b * 32 + dd) * 16 + kq * 4 + kg) * DN + q];
    }

    lc_level<128, 4, 1792>(tid, b, dd, kq, cur, xb, wpk, lc_w, lc_b, 3);
    lc_level<256, 4, 1536>(tid, b, dd, kq, cur, xb, wpk, lc_w, lc_b, 2);
    lc_level<512, 2, 1024>(tid, b, dd, kq, cur, xb, wpk, lc_w, lc_b, 1);
    lc_level<1024, 1, 0>  (tid, b, dd, kq, cur, xb, wpk, lc_w, lc_b, 0);

    __syncthreads();
    for (int e = tid; e < 2048; e += 256) {
        float s = cur[e] + cur[2048 + e] + cur[4096 + e] + cur[6144 + e];
        g_sum[((size_t)(kq * 16 + b) * 32 + dd) * LL + e] = s;
    }
}

// ---------------- K6: U = (sum over dd) @ Wrev ----------------
__global__ void k_final(const float* __restrict__ Wrev, float* __restrict__ out) {
    __shared__ float sW[DLAT * DD];
    __shared__ float ss[DLAT * 33];
    int tid = threadIdx.x;
    int b   = blockIdx.x >> 6;
    int t0  = (blockIdx.x & 63) << 5;
    for (int e = tid; e < DLAT * DD; e += 256) sW[e] = Wrev[e];
    for (int e = tid; e < 1024; e += 256) {
        int dd = e >> 5, tt = e & 31;
        float s = 0.f;
#pragma unroll
        for (int kq = 0; kq < 4; ++kq)
            s += g_sum[((size_t)(kq * 16 + b) * 32 + dd) * LL + t0 + tt];
        ss[dd * 33 + tt] = s;
    }
    __syncthreads();
    for (int e = tid; e < 2048; e += 256) {
        int tt = e >> 6, Dj = e & 63;
        float acc = 0.f;
#pragma unroll
        for (int dd = 0; dd < DLAT; ++dd) acc += ss[dd * 33 + tt] * sW[dd * DD + Dj];
        out[((size_t)b * LL + t0 + tt) * DD + Dj] = acc;
    }
}

// ---------------- launch ----------------
extern "C" void kernel_launch(void* const* d_in, const int* in_sizes, int n_in,
                              void* d_out, int out_size) {
    const float* seq    = (const float*)d_in[0];
    const float* coeffs = (const float*)d_in[1];
    const float* tme    = (const float*)d_in[2];
    const float* ts     = (const float*)d_in[3];
    const float* Wg     = (const float*)d_in[4];
    const float* Wh     = (const float*)d_in[5];
    const float* denseW = (const float*)d_in[6];
    const float* lcw    = (const float*)d_in[7];
    const float* lcb    = (const float*)d_in[8];
    const float* Wrev   = (const float*)d_in[9];
    float* out = (float*)d_out;
    int Lts = in_sizes[3];

    const int waveSmem = (8192 + 2 * 2112 + 2304) * 4;   // 58,880 B
    cudaFuncSetAttribute(k_wave, cudaFuncAttributeMaxDynamicSharedMemorySize, waveSmem);

    k_v<<<BB * (LL / 32), 128>>>(seq, Wg, coeffs, tme, ts, Wh, Lts);
    k_haar<<<BB * KK, 128>>>();
    k_dense3<<<DLAT * KK, 256>>>(denseW);
    k_wave<<<BB * DLAT * 4, 256, waveSmem>>>(lcw, lcb);
    k_final<<<BB * (LL / 32), 256>>>(Wrev, out);
}

// round 14
// speedup vs baseline: 1.1740x; 1.1740x over previous
#include <cuda_runtime.h>
#include <cstdint>

#define BB 16
#define LL 2048
#define DD 64
#define DLAT 32
#define KK 16
#define DN 128

#define SQCF 0.70710678118654752440f

// ---------------- f32x2 helpers (sm_100+) ----------------
#define PACKF2(d, a, b) asm("mov.b64 %0, {%1, %2};" : "=l"(d) : "f"(a), "f"(b))
#define FMAF2(d, a, b)  asm("fma.rn.f32x2 %0, %1, %2, %0;" : "+l"(d) : "l"(a), "l"(b))
#define UNPKF2(lo, hi, d) asm("mov.b64 {%0, %1}, %2;" : "=f"(lo), "=f"(hi) : "l"(d))

// ---------------- scratch (device globals) ----------------
__device__ float g_v[BB * KK * LL];                      // 2 MB
__device__ float g_det[BB * KK * 1920];                  // 2 MB
__device__ float g_app[BB * KK * 1920];                  // 2 MB
__device__ float g_curA[(size_t)BB * DLAT * KK * DN];    // 4 MB (dense output)
__device__ float g_sum[(size_t)4 * BB * DLAT * LL];      // 16 MB (per-kquarter sums)

// ---------------- K2: fused z + v ----------------
__global__ void __launch_bounds__(128) k_v(const float* __restrict__ seq,
                                           const float* __restrict__ Wg,
                                           const float* __restrict__ coeffs,
                                           const float* __restrict__ tme,
                                           const float* __restrict__ ts,
                                           const float* __restrict__ Wh, int Lts) {
    __shared__ __align__(16) float sWh[32 * 256];   // 32 KB (also staging for Wg|seq)
    __shared__ float sder[32 * 65];
    __shared__ __align__(16) float sz[32 * 36];     // z rows, padded stride 36
    __shared__ int   si[32];
    __shared__ float sinv[32];

    int tid = threadIdx.x;
    int b   = blockIdx.x >> 6;
    int l0  = (blockIdx.x & 63) << 5;

    for (int e = tid; e < 2048; e += 128) sWh[e] = Wg[e];
    {
        const float4* sp = (const float4*)(seq + ((size_t)b * LL + l0) * DD);
        for (int e = tid; e < 512; e += 128) ((float4*)(sWh + 2048))[e] = sp[e];
    }
    if (tid < 32) {
        float t = tme[l0 + tid];
        int lo = 0, hi = Lts;
        while (lo < hi) { int mid = (lo + hi) >> 1; if (ts[mid] <= t) lo = mid + 1; else hi = mid; }
        int i = lo - 1;
        if (i < 0) i = 0;
        if (i > Lts - 2) i = Lts - 2;
        si[tid]   = i;
        sinv[tid] = 1.f / (ts[i + 1] - ts[i]);
    }
    __syncthreads();

    for (int e = tid; e < 1024; e += 128) {
        int r = e >> 5, j = e & 31;
        float acc = 0.f;
#pragma unroll
        for (int Dd = 0; Dd < DD; ++Dd)
            acc += sWh[2048 + r * DD + Dd] * sWh[Dd * DLAT + j];
        sz[r * 36 + j] = fmaxf(acc, 0.f);
    }
    for (int e = tid; e < 2048; e += 128) {
        int lt = e >> 6, Dg = e & 63;
        int i  = si[lt];
        float a = coeffs[((size_t)b * LL + i + 1) * DD + Dg];
        float c = coeffs[((size_t)b * LL + i) * DD + Dg];
        sder[lt * 65 + Dg] = (a - c) * sinv[lt];
    }
    __syncthreads();

    int kkq = tid & 3;
    int kk0 = kkq * 4;
    int lt  = tid >> 2;

    unsigned long long zs[32];
    {
        const float4* zp = (const float4*)(sz + lt * 36);
#pragma unroll
        for (int q = 0; q < 8; ++q) {
            float4 z4 = zp[q];
            PACKF2(zs[q * 4 + 0], z4.x, z4.x);
            PACKF2(zs[q * 4 + 1], z4.y, z4.y);
            PACKF2(zs[q * 4 + 2], z4.z, z4.z);
            PACKF2(zs[q * 4 + 3], z4.w, z4.w);
        }
    }

    float acc0 = 0.f, acc1 = 0.f, acc2 = 0.f, acc3 = 0.f;
#pragma unroll 1
    for (int ch = 0; ch < 4; ++ch) {
        __syncthreads();
        const float4* src4 = (const float4*)Wh + ch * 64;
        for (int e = tid; e < 2048; e += 128) {
            int ddr = e >> 6, c4 = e & 63;
            ((float4*)sWh)[ddr * 64 + c4] = src4[(size_t)ddr * 256 + c4];
        }
        __syncthreads();
#pragma unroll 2
        for (int Dl = 0; Dl < 16; ++Dl) {
            unsigned long long h01 = 0ULL, h23 = 0ULL;
            const ulonglong2* wb = reinterpret_cast<const ulonglong2*>(sWh + Dl * 16 + kk0);
#pragma unroll
            for (int ddq = 0; ddq < 32; ++ddq) {
                ulonglong2 w = wb[ddq * 64];
                FMAF2(h01, zs[ddq], w.x);
                FMAF2(h23, zs[ddq], w.y);
            }
            float f0, f1, f2, f3;
            UNPKF2(f0, f1, h01);
            UNPKF2(f2, f3, h23);
            float dv = sder[lt * 65 + ch * 16 + Dl];
            acc0 += fmaxf(f0, 0.f) * dv;
            acc1 += fmaxf(f1, 0.f) * dv;
            acc2 += fmaxf(f2, 0.f) * dv;
            acc3 += fmaxf(f3, 0.f) * dv;
        }
    }
    size_t vb = (size_t)b * KK;
    g_v[(vb + kk0 + 0) * LL + l0 + lt] = acc0;
    g_v[(vb + kk0 + 1) * LL + l0 + lt] = acc1;
    g_v[(vb + kk0 + 2) * LL + l0 + lt] = acc2;
    g_v[(vb + kk0 + 3) * LL + l0 + lt] = acc3;
}

// ---------------- K3: 4-level Haar decomposition ----------------
__global__ void k_haar() {
    __shared__ float s0[2048];
    __shared__ float s1[1024];
    int bk  = blockIdx.x;
    int tid = threadIdx.x;
    const float* row = g_v + (size_t)bk * LL;
    for (int i = tid; i < 2048; i += 128) s0[i] = row[i];
    __syncthreads();
    int n = 2048, off = 0;
    float* src = s0;
    float* dst = s1;
    for (int lev = 0; lev < 4; ++lev) {
        int half = n >> 1;
        for (int t = tid; t < half; t += 128) {
            float a = src[2 * t], bv = src[2 * t + 1];
            float cA = (a + bv) * SQCF;
            float cD = (a - bv) * SQCF;
            dst[t] = cA;
            g_det[(size_t)bk * 1920 + off + t] = cD;
            g_app[(size_t)bk * 1920 + off + t] = cA;
        }
        __syncthreads();
        off += half; n = half;
        float* tmp = src; src = dst; dst = tmp;
    }
}

// ---------------- K4: fused 3-round dense chain (R10/R12 version) --------
__global__ void __launch_bounds__(256) k_dense3(const float* __restrict__ W) {
    __shared__ __align__(16) float sx[2][128 * 20];   // 20.5 KB
    __shared__ __align__(16) float Ws[128 * 36];      // 18.4 KB
    int tid = threadIdx.x;
    int dd  = blockIdx.x >> 4;
    int kk  = blockIdx.x & 15;
    int t   = tid & 127;
    int bh  = tid >> 7;
    int prow = tid >> 3;
    int pc4  = tid & 7;

    for (int e = tid; e < 2048; e += 256) {
        int b = e >> 7, q = e & 127;
        sx[0][q * 20 + b] = g_app[(size_t)(b * 16 + kk) * 1920 + 1792 + q];
    }

    int src = 0;
#pragma unroll 1
    for (int r = 0; r < 3; ++r) {
        const float4* Wr4 = (const float4*)(W + ((size_t)r * 512 + dd * 16 + kk) * (DN * DN));
        float4 pf[4];
#pragma unroll
        for (int i = 0; i < 4; ++i)
            pf[i] = Wr4[(prow + i * 32) * 32 + pc4];

        unsigned long long a0 = 0ULL, a1 = 0ULL, a2 = 0ULL, a3 = 0ULL;
#pragma unroll 1
        for (int ch = 0; ch < 4; ++ch) {
            __syncthreads();
#pragma unroll
            for (int i = 0; i < 4; ++i)
                *(float4*)&Ws[(prow + i * 32) * 36 + pc4 * 4] = pf[i];
            if (ch < 3) {
#pragma unroll
                for (int i = 0; i < 4; ++i)
                    pf[i] = Wr4[(prow + i * 32) * 32 + (ch + 1) * 8 + pc4];
            }
            __syncthreads();
#pragma unroll
            for (int q4 = 0; q4 < 8; ++q4) {
                float4 w = *(const float4*)&Ws[t * 36 + q4 * 4];
                int qb = (ch * 8 + q4) * 4;
#pragma unroll
                for (int s = 0; s < 4; ++s) {
                    float wv = (s == 0) ? w.x : (s == 1) ? w.y : (s == 2) ? w.z : w.w;
                    unsigned long long ws;
                    PACKF2(ws, wv, wv);
                    const ulonglong2* xv =
                        (const ulonglong2*)&sx[src][(qb + s) * 20 + bh * 8];
                    ulonglong2 xa = xv[0];
                    FMAF2(a0, ws, xa.x);
                    FMAF2(a1, ws, xa.y);
                    ulonglong2 xb2 = xv[1];
                    FMAF2(a2, ws, xb2.x);
                    FMAF2(a3, ws, xb2.y);
                }
            }
        }
        float f0, f1, f2, f3, f4, f5, f6, f7;
        UNPKF2(f0, f1, a0); UNPKF2(f2, f3, a1);
        UNPKF2(f4, f5, a2); UNPKF2(f6, f7, a3);
        if (r < 2) {
            int ds = src ^ 1;
            *(float4*)&sx[ds][t * 20 + bh * 8]     = make_float4(f0, f1, f2, f3);
            *(float4*)&sx[ds][t * 20 + bh * 8 + 4] = make_float4(f4, f5, f6, f7);
            src = ds;
        } else {
            float f[8] = {f0, f1, f2, f3, f4, f5, f6, f7};
#pragma unroll
            for (int i = 0; i < 8; ++i) {
                int b = bh * 8 + i;
                g_curA[(((size_t)b * 32 + dd) * 16 + kk) * DN + t] = f[i];
            }
        }
    }
}

// ---------------- K5: fused wavelet reconstruction (R12 conv, 4 CTA/SM diet) --
// block = (b, dd, kq); 4 kk per block; cur[4][2048] in SMEM across all levels.
// smem floats: cur 8192 | xb 2*2080 | wpk 1056  => 53,632 B => 4 CTAs/SM
// Levels 3/2 run G=2 (2 groups) to keep wpk at 528 u64.

template <int Ll, int G, int OFF>
__device__ __forceinline__ void lc_level(int tid, int b, int dd, int kq,
                                         float* __restrict__ cur,
                                         float* __restrict__ xb,
                                         float* __restrict__ wpk,
                                         const float* __restrict__ lc_w,
                                         const float* __restrict__ lc_b,
                                         int lev) {
    constexpr int stride = Ll + 4;
    constexpr int R = Ll >> 3;
    constexpr int ng = 4 / G;
    constexpr int XB = 2080;
    constexpr int total = (G * Ll) >> 2;
    constexpr int lq = Ll >> 2;

    __syncthreads();
    for (int e = tid; e < 2 * XB; e += 256) xb[e] = 0.f;

#pragma unroll 1
    for (int grp = 0; grp < ng; ++grp) {
        int kg0 = grp * G;
        __syncthreads();
        // pack weights+bias pairs for this group's G kk
        constexpr int P = 3 * G * 88;
        for (int e = tid; e < P; e += 256) {
            int j  = e / (G * 88);
            int r2 = e - j * (G * 88);
            int kg = r2 / 88;
            int r3 = r2 - kg * 88;
            int seg = r3 / 11;
            int i   = r3 - seg * 11;
            int kk  = kq * 4 + kg0 + kg;
            size_t base = ((size_t)((lev * 3 + j) * 32 + dd) * 16 + kk);
            float lo, hi;
            if (i < 10) {
                int i2 = i / 5, f = i - i2 * 5;
                lo = lc_w[base * 160 + i2 * 40 + seg * 5 + f];
                hi = lc_w[base * 160 + 80 + i2 * 40 + seg * 5 + f];
            } else {
                lo = lc_b[base * 16 + seg];
                hi = lc_b[base * 16 + 8 + seg];
            }
            ((float2*)wpk)[e] = make_float2(lo, hi);
        }
        // init chi rows into buf0 interior (+2)
        for (int e = tid; e < G * 2 * Ll; e += 256) {
            int row = e / Ll, t = e - row * Ll;
            int kg = row >> 1, i = row & 1;
            int kk = kq * 4 + kg0 + kg;
            const float* srcg = (i == 0) ? g_det : g_app;
            xb[row * stride + 2 + t] = srcg[(size_t)(b * 16 + kk) * 1920 + OFF + t];
        }
        __syncthreads();

        int srcb = 0;
#pragma unroll 1
        for (int j = 0; j < 3; ++j) {
            if (tid < total) {
                int kg = tid / lq;
                int t0 = (tid - kg * lq) << 2;
                int seg = t0 / R;          // R multiple of 4 => t0..t0+3 same seg
                const unsigned long long* wp =
                    (const unsigned long long*)wpk + ((size_t)((j * G + kg) * 8 + seg)) * 11;
                unsigned long long Wt[10];
#pragma unroll
                for (int i = 0; i < 10; ++i) Wt[i] = wp[i];
                unsigned long long Bp = wp[10];

                const float* b0 = &xb[srcb * XB + (kg * 2 + 0) * stride + t0];
                const float* b1 = &xb[srcb * XB + (kg * 2 + 1) * stride + t0];
                float4 A0 = *(const float4*)b0;
                float4 A1 = *(const float4*)(b0 + 4);
                float4 C0 = *(const float4*)b1;
                float4 C1 = *(const float4*)(b1 + 4);
                float av[8] = {A0.x, A0.y, A0.z, A0.w, A1.x, A1.y, A1.z, A1.w};
                float cv[8] = {C0.x, C0.y, C0.z, C0.w, C1.x, C1.y, C1.z, C1.w};
                unsigned long long sa[8], sc[8];
#pragma unroll
                for (int i = 0; i < 8; ++i) {
                    PACKF2(sa[i], av[i], av[i]);
                    PACKF2(sc[i], cv[i], cv[i]);
                }
                float o0[4], o1[4];
#pragma unroll
                for (int p = 0; p < 4; ++p) {
                    unsigned long long acc = Bp;
#pragma unroll
                    for (int f = 0; f < 5; ++f) FMAF2(acc, Wt[f], sa[p + f]);
#pragma unroll
                    for (int f = 0; f < 5; ++f) FMAF2(acc, Wt[5 + f], sc[p + f]);
                    float lo, hi;
                    UNPKF2(lo, hi, acc);
                    o0[p] = fmaxf(lo, 0.f);
                    o1[p] = fmaxf(hi, 0.f);
                }
                float* d0 = &xb[(srcb ^ 1) * XB + (kg * 2 + 0) * stride + 2 + t0];
                float* d1 = &xb[(srcb ^ 1) * XB + (kg * 2 + 1) * stride + 2 + t0];
                *(float2*)d0       = make_float2(o0[0], o0[1]);
                *(float2*)(d0 + 2) = make_float2(o0[2], o0[3]);
                *(float2*)d1       = make_float2(o1[0], o1[1]);
                *(float2*)(d1 + 2) = make_float2(o1[2], o1[3]);
            }
            __syncthreads();
            srcb ^= 1;
        }

        // combine + in-place haar_rec (srcb == 1 => final data in xb[XB..])
        constexpr int nel = G * Ll;
        float2 rv[4];
        int cnt = 0;
        for (int e = tid; e < nel; e += 256) {
            int kg = e / Ll, t = e - kg * Ll;
            float X0 = xb[XB + (kg * 2 + 0) * stride + 2 + t];
            float X1 = xb[XB + (kg * 2 + 1) * stride + 2 + t] +
                       cur[(kg0 + kg) * 2048 + t];
            rv[cnt++] = make_float2((X1 + X0) * SQCF, (X1 - X0) * SQCF);
        }
        __syncthreads();
        cnt = 0;
        for (int e = tid; e < nel; e += 256) {
            int kg = e / Ll, t = e - kg * Ll;
            *(float2*)&cur[(kg0 + kg) * 2048 + 2 * t] = rv[cnt++];
        }
        __syncthreads();
    }
}

__global__ void __launch_bounds__(256, 4) k_wave(const float* __restrict__ lc_w,
                                                 const float* __restrict__ lc_b) {
    extern __shared__ float sm[];
    float* cur = sm;                 // 4*2048 = 8192
    float* xb  = sm + 8192;          // 2*2080 = 4160
    float* wpk = sm + 8192 + 4160;   // 1056

    int tid = threadIdx.x;
    int kq  = blockIdx.x & 3;
    int dd  = (blockIdx.x >> 2) & 31;
    int b   = blockIdx.x >> 7;

    for (int e = tid; e < 512; e += 256) {
        int kg = e >> 7, q = e & 127;
        cur[kg * 2048 + q] =
            g_curA[(((size_t)b * 32 + dd) * 16 + kq * 4 + kg) * DN + q];
    }

    lc_level<128, 2, 1792>(tid, b, dd, kq, cur, xb, wpk, lc_w, lc_b, 3);
    lc_level<256, 2, 1536>(tid, b, dd, kq, cur, xb, wpk, lc_w, lc_b, 2);
    lc_level<512, 2, 1024>(tid, b, dd, kq, cur, xb, wpk, lc_w, lc_b, 1);
    lc_level<1024, 1, 0>  (tid, b, dd, kq, cur, xb, wpk, lc_w, lc_b, 0);

    __syncthreads();
    for (int e = tid; e < 2048; e += 256) {
        float s = cur[e] + cur[2048 + e] + cur[4096 + e] + cur[6144 + e];
        g_sum[((size_t)(kq * 16 + b) * 32 + dd) * LL + e] = s;
    }
}

// ---------------- K6: U = (sum over dd) @ Wrev ----------------
__global__ void k_final(const float* __restrict__ Wrev, float* __restrict__ out) {
    __shared__ float sW[DLAT * DD];
    __shared__ float ss[DLAT * 33];
    int tid = threadIdx.x;
    int b   = blockIdx.x >> 6;
    int t0  = (blockIdx.x & 63) << 5;
    for (int e = tid; e < DLAT * DD; e += 256) sW[e] = Wrev[e];
    for (int e = tid; e < 1024; e += 256) {
        int dd = e >> 5, tt = e & 31;
        float s = 0.f;
#pragma unroll
        for (int kq = 0; kq < 4; ++kq)
            s += g_sum[((size_t)(kq * 16 + b) * 32 + dd) * LL + t0 + tt];
        ss[dd * 33 + tt] = s;
    }
    __syncthreads();
    for (int e = tid; e < 2048; e += 256) {
        int tt = e >> 6, Dj = e & 63;
        float acc = 0.f;
#pragma unroll
        for (int dd = 0; dd < DLAT; ++dd) acc += ss[dd * 33 + tt] * sW[dd * DD + Dj];
        out[((size_t)b * LL + t0 + tt) * DD + Dj] = acc;
    }
}

// ---------------- launch ----------------
extern "C" void kernel_launch(void* const* d_in, const int* in_sizes, int n_in,
                              void* d_out, int out_size) {
    const float* seq    = (const float*)d_in[0];
    const float* coeffs = (const float*)d_in[1];
    const float* tme    = (const float*)d_in[2];
    const float* ts     = (const float*)d_in[3];
    const float* Wg     = (const float*)d_in[4];
    const float* Wh     = (const float*)d_in[5];
    const float* denseW = (const float*)d_in[6];
    const float* lcw    = (const float*)d_in[7];
    const float* lcb    = (const float*)d_in[8];
    const float* Wrev   = (const float*)d_in[9];
    float* out = (float*)d_out;
    int Lts = in_sizes[3];

    const int waveSmem = (8192 + 2 * 2080 + 1056) * 4;   // 53,632 B -> 4 CTAs/SM
    cudaFuncSetAttribute(k_wave, cudaFuncAttributeMaxDynamicSharedMemorySize, waveSmem);

    k_v<<<BB * (LL / 32), 128>>>(seq, Wg, coeffs, tme, ts, Wh, Lts);
    k_haar<<<BB * KK, 128>>>();
    k_dense3<<<DLAT * KK, 256>>>(denseW);
    k_wave<<<BB * DLAT * 4, 256, waveSmem>>>(lcw, lcb);
    k_final<<<BB * (LL / 32), 256>>>(Wrev, out);
}